// round 5
// baseline (speedup 1.0000x reference)
#include <cuda_runtime.h>

// x[32, 336, 32, 32] fp32, moving-avg k=25 (replicate pad), seasonal period 24
#define BB     32
#define CC     336
#define KS     25
#define PE     24
#define NG     (CC / PE)          // 14
#define HWW    1024
#define NCOL   (BB * HWW)         // 32768 columns
#define NELEM  ((size_t)BB * CC * HWW)

#define COLS    16                // fp32 columns per block
#define NTHREAD (COLS * NG)       // 224

__global__ __launch_bounds__(NTHREAD, 7)
void decomp_kernel(const float* __restrict__ x,
                   float* __restrict__ To,
                   float* __restrict__ So,
                   float* __restrict__ Ro)
{
    __shared__ float xd_s[NG][PE][COLS];  // detrended values (21 KB)
    __shared__ float acc[PE][COLS];       // seasonal means   (1.5 KB)

    const int tx = threadIdx.x;           // [0,16) column lane
    const int g  = threadIdx.y;           // [0,14) channel group
    const int col = blockIdx.x * COLS + tx;
    const int b  = col >> 10;
    const int hw = col & (HWW - 1);

    const size_t base = (size_t)b * CC * HWW + hw;
    const float* __restrict__ xp = x + base;

    const float inv_k = 1.0f / (float)KS;
    const float inv_g = 1.0f / (float)NG;
    const int   c0    = g * PE;

    // initial window sum at c = c0: sum_{j=-12..12} x[clamp(c0+j)]
    float wsum = 0.0f;
    #pragma unroll
    for (int j = -12; j <= 12; j++) {
        int cc = c0 + j;
        cc = cc < 0 ? 0 : (cc > CC - 1 ? CC - 1 : cc);
        wsum += xp[(size_t)cc * HWW];
    }

    // ---- Pass A: trend (write To), stash detrended in smem ----
    #pragma unroll
    for (int p = 0; p < PE; p++) {
        const int c = c0 + p;
        float T  = wsum * inv_k;
        float xc = xp[(size_t)c * HWW];
        __stcs(&To[base + (size_t)c * HWW], T);   // evict-first: never re-read
        xd_s[g][p][tx] = xc - T;
        int cin  = c + 13; if (cin  > CC - 1) cin  = CC - 1;
        int cout = c - 12; if (cout < 0)      cout = 0;
        wsum += xp[(size_t)cin * HWW] - xp[(size_t)cout * HWW];
    }

    __syncthreads();

    // ---- Cross-group reduction: each thread owns (p, t) pairs ----
    {
        const int lin = threadIdx.y * COLS + threadIdx.x;
        #pragma unroll
        for (int idx = lin; idx < PE * COLS; idx += NTHREAD) {
            const int p = idx / COLS;
            const int t = idx % COLS;
            float s = 0.0f;
            #pragma unroll
            for (int gg = 0; gg < NG; gg++) s += xd_s[gg][p][t];
            acc[p][t] = s * inv_g;
        }
    }

    __syncthreads();

    // ---- Pass B: emit seasonal + residual from smem (no global re-reads) ----
    #pragma unroll
    for (int p = 0; p < PE; p++) {
        const int c = c0 + p;
        float S  = acc[p][tx];
        float xd = xd_s[g][p][tx];
        __stcs(&So[base + (size_t)c * HWW], S);
        __stcs(&Ro[base + (size_t)c * HWW], xd - S);
    }
}

extern "C" void kernel_launch(void* const* d_in, const int* in_sizes, int n_in,
                              void* d_out, int out_size)
{
    const float* x = (const float*)d_in[0];
    float* out = (float*)d_out;
    float* To = out;
    float* So = out + NELEM;
    float* Ro = out + 2 * NELEM;
    dim3 blk(COLS, NG);
    decomp_kernel<<<NCOL / COLS, blk>>>(x, To, So, Ro);
}

// round 6
// speedup vs baseline: 1.1105x; 1.1105x over previous
#include <cuda_runtime.h>

// x[32, 336, 32, 32] fp32, moving-avg k=25 (replicate pad), seasonal period 24
#define BB     32
#define CC     336
#define KS     25
#define PE     24
#define NG     (CC / PE)          // 14
#define HWW    1024
#define NCOL   (BB * HWW)         // 32768 columns
#define NELEM  ((size_t)BB * CC * HWW)

#define COLS    32                // fp32 columns per block (one warp-width -> 128B wavefronts)
#define NTHREAD (COLS * NG)       // 448

__global__ __launch_bounds__(NTHREAD, 4)   // force 36-reg budget -> 4 blocks/SM
void decomp_kernel(const float* __restrict__ x,
                   float* __restrict__ To,
                   float* __restrict__ So,
                   float* __restrict__ Ro)
{
    __shared__ float xd_s[NG][PE][COLS];  // detrended values (42 KB)
    __shared__ float acc[PE][COLS];       // seasonal means   (3 KB)

    const int tx = threadIdx.x;           // [0,32) column lane
    const int g  = threadIdx.y;           // [0,14) channel group (one warp each)
    const int col = blockIdx.x * COLS + tx;
    const int b  = col >> 10;
    const int hw = col & (HWW - 1);

    const size_t base = (size_t)b * CC * HWW + hw;
    const float* __restrict__ xp = x + base;

    const float inv_k = 1.0f / (float)KS;
    const float inv_g = 1.0f / (float)NG;
    const int   c0    = g * PE;

    // initial window sum at c = c0: sum_{j=-12..12} x[clamp(c0+j)]
    float wsum = 0.0f;
    #pragma unroll
    for (int j = -12; j <= 12; j++) {
        int cc = c0 + j;
        cc = cc < 0 ? 0 : (cc > CC - 1 ? CC - 1 : cc);
        wsum += xp[(size_t)cc * HWW];
    }

    // ---- Pass A: trend (write To), stash detrended in smem ----
    #pragma unroll
    for (int p = 0; p < PE; p++) {
        const int c = c0 + p;
        float T  = wsum * inv_k;
        float xc = xp[(size_t)c * HWW];
        __stcs(&To[base + (size_t)c * HWW], T);   // evict-first: never re-read
        xd_s[g][p][tx] = xc - T;
        int cin  = c + 13; if (cin  > CC - 1) cin  = CC - 1;
        int cout = c - 12; if (cout < 0)      cout = 0;
        wsum += xp[(size_t)cin * HWW] - xp[(size_t)cout * HWW];
    }

    __syncthreads();

    // ---- Cross-group reduction (no atomics): each thread owns (p, t) pairs ----
    {
        const int lin = threadIdx.y * COLS + threadIdx.x;
        #pragma unroll
        for (int idx = lin; idx < PE * COLS; idx += NTHREAD) {
            const int p = idx >> 5;
            const int t = idx & 31;
            float s = 0.0f;
            #pragma unroll
            for (int gg = 0; gg < NG; gg++) s += xd_s[gg][p][t];
            acc[p][t] = s * inv_g;
        }
    }

    __syncthreads();

    // ---- Pass B: emit seasonal + residual from smem (no global re-reads) ----
    #pragma unroll
    for (int p = 0; p < PE; p++) {
        const int c = c0 + p;
        float S  = acc[p][tx];
        float xd = xd_s[g][p][tx];
        __stcs(&So[base + (size_t)c * HWW], S);
        __stcs(&Ro[base + (size_t)c * HWW], xd - S);
    }
}

extern "C" void kernel_launch(void* const* d_in, const int* in_sizes, int n_in,
                              void* d_out, int out_size)
{
    const float* x = (const float*)d_in[0];
    float* out = (float*)d_out;
    float* To = out;
    float* So = out + NELEM;
    float* Ro = out + 2 * NELEM;
    dim3 blk(COLS, NG);
    decomp_kernel<<<NCOL / COLS, blk>>>(x, To, So, Ro);
}

// round 7
// speedup vs baseline: 1.3279x; 1.1957x over previous
#include <cuda_runtime.h>

// x[32, 336, 32, 32] fp32, moving-avg k=25 (replicate pad), seasonal period 24
#define BB     32
#define CC     336
#define KS     25
#define PE     24
#define NG     (CC / PE)          // 14
#define HWW    1024
#define HW4    (HWW / 4)          // 256 float4 per (b,c) plane
#define NCOL4  (BB * HW4)         // 8192 float4-columns
#define NELEM  ((size_t)BB * CC * HWW)

#define COLS4   8                 // float4 columns per block
#define NTHREAD (COLS4 * NG)      // 112

__device__ __forceinline__ float4 f4_add(float4 a, float4 b) {
    return make_float4(a.x + b.x, a.y + b.y, a.z + b.z, a.w + b.w);
}
__device__ __forceinline__ float4 f4_sub(float4 a, float4 b) {
    return make_float4(a.x - b.x, a.y - b.y, a.z - b.z, a.w - b.w);
}
__device__ __forceinline__ float4 f4_scale(float4 a, float s) {
    return make_float4(a.x * s, a.y * s, a.z * s, a.w * s);
}

__global__ __launch_bounds__(NTHREAD, 4)
void decomp_kernel(const float4* __restrict__ x,
                   float4* __restrict__ To,
                   float4* __restrict__ So,
                   float4* __restrict__ Ro)
{
    __shared__ float4 xd_s[NG][PE][COLS4];  // detrended (43 KB)
    __shared__ float4 acc[PE][COLS4];       // seasonal means (3 KB)

    const int tx = threadIdx.x;             // [0,8) float4 column lane
    const int g  = threadIdx.y;             // [0,14) channel group
    const int col4 = blockIdx.x * COLS4 + tx;
    const int b   = col4 >> 8;              // col4 / 256
    const int hw4 = col4 & (HW4 - 1);

    const size_t base = (size_t)b * CC * HW4 + hw4;
    const float4* __restrict__ xp = x + base;

    const float inv_k = 1.0f / (float)KS;
    const float inv_g = 1.0f / (float)NG;
    const int   c0    = g * PE;

    // initial window sum at c = c0: sum_{j=-12..12} x[clamp(c0+j)]
    float4 wsum = make_float4(0.f, 0.f, 0.f, 0.f);
    #pragma unroll
    for (int j = -12; j <= 12; j++) {
        int cc = c0 + j;
        cc = cc < 0 ? 0 : (cc > CC - 1 ? CC - 1 : cc);
        wsum = f4_add(wsum, xp[(size_t)cc * HW4]);
    }

    // ---- Pass A: trend (write To), stash detrended in smem ----
    #pragma unroll
    for (int p = 0; p < PE; p++) {
        const int c = c0 + p;
        float4 T  = f4_scale(wsum, inv_k);
        float4 xc = xp[(size_t)c * HW4];
        __stcs(&To[base + (size_t)c * HW4], T);   // evict-first: never re-read
        xd_s[g][p][tx] = f4_sub(xc, T);
        int cin  = c + 13; if (cin  > CC - 1) cin  = CC - 1;
        int cout = c - 12; if (cout < 0)      cout = 0;
        wsum = f4_add(wsum, f4_sub(xp[(size_t)cin * HW4], xp[(size_t)cout * HW4]));
    }

    __syncthreads();

    // ---- Cross-group reduction: each thread owns (p, t) pairs ----
    {
        const int lin = threadIdx.y * COLS4 + threadIdx.x;
        #pragma unroll
        for (int idx = lin; idx < PE * COLS4; idx += NTHREAD) {
            const int p = idx >> 3;            // / COLS4
            const int t = idx & (COLS4 - 1);
            float4 s = make_float4(0.f, 0.f, 0.f, 0.f);
            #pragma unroll
            for (int gg = 0; gg < NG; gg++) s = f4_add(s, xd_s[gg][p][t]);
            acc[p][t] = f4_scale(s, inv_g);
        }
    }

    __syncthreads();

    // ---- Pass B: emit seasonal + residual from smem (no global re-reads) ----
    #pragma unroll
    for (int p = 0; p < PE; p++) {
        const int c = c0 + p;
        float4 S  = acc[p][tx];
        float4 xd = xd_s[g][p][tx];
        __stcs(&So[base + (size_t)c * HW4], S);
        __stcs(&Ro[base + (size_t)c * HW4], f4_sub(xd, S));
    }
}

extern "C" void kernel_launch(void* const* d_in, const int* in_sizes, int n_in,
                              void* d_out, int out_size)
{
    const float4* x = (const float4*)d_in[0];
    float* out = (float*)d_out;
    float4* To = (float4*)out;
    float4* So = (float4*)(out + NELEM);
    float4* Ro = (float4*)(out + 2 * NELEM);
    dim3 blk(COLS4, NG);
    decomp_kernel<<<NCOL4 / COLS4, blk>>>(x, To, So, Ro);
}